// round 6
// baseline (speedup 1.0000x reference)
#include <cuda_runtime.h>
#include <cuda_bf16.h>

// ============================================================================
// Symmetric-contraction (MACE-style) kernel — Horner-factorized.
//
// res[n,c] = sum_{x<=i<=j} C2[c,x,i,j] f_x f_i f_j
//          + sum_{x<=i}    C1[c,x,i]   f_x f_i
//          + sum_x         C0[c,x]     f_x
// evaluated as
// res = sum_x f_x * ( C0[x] + sum_{i>=x} f_i * ( C1[x,i] + sum_{j>=i} C2[x,i,j] f_j ) )
//
// -> 968 fma.rn.f32x2 per thread (2 atoms packed), ZERO multiplies.
// Coefficients streamed from shared memory in exact consumption order,
// duplicated into both f32 halves of a u64 so one LDS.128 feeds two FMAs.
// ============================================================================

#define NPOS 968            // 16 (C0) + 136 (C1) + 816 (C2), Horner order
#define CCH  64
#define NI   16

__device__ float              g_Ustream[NPOS * 120];     // symmetrized U rows
__device__ unsigned long long g_Coef[CCH * NPOS];        // per-channel stream (dup'd)

// Decode stream position -> entry type + indices.
// Horner stream order (matches main-kernel consumption exactly):
//   for x in 0..15:
//     [C0(x)]
//     for i in x..15:
//       [C1(x,i)]
//       for j in i..15: [C2(x,i,j)]
__device__ __forceinline__ void decode_pos(int pos, int& ty, int& a, int& b, int& e) {
    int pp = pos;
    for (int xx = 0; xx < 16; ++xx) {
        if (pp == 0) { ty = 0; a = xx; b = 0; e = 0; return; }
        pp--;
        for (int ii = xx; ii < 16; ++ii) {
            if (pp == 0) { ty = 1; a = xx; b = ii; e = 0; return; }
            pp--;
            int cnt = 16 - ii;
            if (pp < cnt) { ty = 2; a = xx; b = ii; e = ii + pp; return; }
            pp -= cnt;
        }
    }
    ty = 0; a = 0; b = 0; e = 0;   // unreachable
}

// ---------------------------------------------------------------------------
// P1: symmetrize U tensors into the stream layout. grid = NPOS blocks, 128 thr.
// ---------------------------------------------------------------------------
__global__ void prep_u_kernel(const float* __restrict__ U2,
                              const float* __restrict__ U1,
                              const float* __restrict__ U0) {
    int pos = blockIdx.x;
    int k   = threadIdx.x;
    int ty, a, b, e;
    decode_pos(pos, ty, a, b, e);
    float s = 0.f;
    if (ty == 2) {                       // cubic: sum over distinct perms of (a,b,e)
        if (k >= 120) return;
#define U2AT(x, y, i) U2[((((x) * 16 + (y)) * 16 + (i)) * 120) + k]
        if (a == b && b == e)      s = U2AT(a, a, a);
        else if (a == b)           s = U2AT(a, a, e) + U2AT(a, e, a) + U2AT(e, a, a);
        else if (b == e)           s = U2AT(a, b, b) + U2AT(b, a, b) + U2AT(b, b, a);
        else                       s = U2AT(a, b, e) + U2AT(a, e, b) + U2AT(b, a, e)
                                     + U2AT(b, e, a) + U2AT(e, a, b) + U2AT(e, b, a);
#undef U2AT
    } else if (ty == 1) {                // quadratic: U1[a,b] + U1[b,a]
        if (k >= 8) return;
        s = (a == b) ? U1[(a * 16 + a) * 8 + k]
                     : U1[(a * 16 + b) * 8 + k] + U1[(b * 16 + a) * 8 + k];
    } else {                             // linear
        if (k >= 4) return;
        s = U0[a * 4 + k];
    }
    g_Ustream[pos * 120 + k] = s;
}

// ---------------------------------------------------------------------------
// P2: per-channel coefficient stream = Ustream . w. One thread per (pos, c).
// Values duplicated into both fp32 halves of a u64 for packed FMA.
// ---------------------------------------------------------------------------
__global__ void prep_coef_kernel(const float* __restrict__ w2,
                                 const float* __restrict__ w1,
                                 const float* __restrict__ w0) {
    int idx = blockIdx.x * blockDim.x + threadIdx.x;
    if (idx >= NPOS * CCH) return;
    int pos = idx >> 6;
    int c   = idx & 63;
    int ty, a, b, e;
    decode_pos(pos, ty, a, b, e);
    const float* us = g_Ustream + pos * 120;
    float v = 0.f;
    if (ty == 2) {
#pragma unroll
        for (int k = 0; k < 120; ++k) v += us[k] * w2[k * 64 + c];
    } else if (ty == 1) {
#pragma unroll
        for (int k = 0; k < 8; ++k)   v += us[k] * w1[k * 64 + c];
    } else {
#pragma unroll
        for (int k = 0; k < 4; ++k)   v += us[k] * w0[k * 64 + c];
    }
    unsigned u = __float_as_uint(v);
    g_Coef[c * NPOS + pos] = ((unsigned long long)u << 32) | (unsigned long long)u;
}

// ---------------------------------------------------------------------------
// Main kernel: each thread evaluates the Horner-factorized cubic form for
// 2 atoms (packed f32x2) at one channel. 968 FMA2, no MULs.
// ---------------------------------------------------------------------------
#define FMA2(d, a, b, c) asm("fma.rn.f32x2 %0, %1, %2, %3;" : "=l"(d) : "l"(a), "l"(b), "l"(c))
#define ADD2(d, a, b)    asm("add.rn.f32x2 %0, %1, %2;"     : "=l"(d) : "l"(a), "l"(b))

__global__ __launch_bounds__(256)
void sym_contract_kernel(const float* __restrict__ nf,
                         float* __restrict__ out,
                         int Natoms) {
    __shared__ __align__(16) unsigned long long scoef[NPOS];
    const int c = blockIdx.y;

    for (int i = threadIdx.x; i < NPOS; i += 256)
        scoef[i] = g_Coef[c * NPOS + i];
    __syncthreads();

    const int n0 = blockIdx.x * 512 + threadIdx.x;
    const int n1 = n0 + 256;

    float lo[NI], hi[NI];
#pragma unroll
    for (int i = 0; i < NI; ++i) { lo[i] = 0.f; hi[i] = 0.f; }

    if (n0 < Natoms) {
        const float4* p4 = reinterpret_cast<const float4*>(nf + ((size_t)n0 * 64 + c) * 16);
#pragma unroll
        for (int j = 0; j < 4; ++j) {
            float4 v = p4[j];
            lo[4 * j + 0] = v.x; lo[4 * j + 1] = v.y; lo[4 * j + 2] = v.z; lo[4 * j + 3] = v.w;
        }
    }
    if (n1 < Natoms) {
        const float4* p4 = reinterpret_cast<const float4*>(nf + ((size_t)n1 * 64 + c) * 16);
#pragma unroll
        for (int j = 0; j < 4; ++j) {
            float4 v = p4[j];
            hi[4 * j + 0] = v.x; hi[4 * j + 1] = v.y; hi[4 * j + 2] = v.z; hi[4 * j + 3] = v.w;
        }
    }

    unsigned long long F[NI];
#pragma unroll
    for (int i = 0; i < NI; ++i) {
        asm("mov.b64 %0, {%1, %2};" : "=l"(F[i])
            : "r"(__float_as_uint(lo[i])), "r"(__float_as_uint(hi[i])));
    }

    const ulonglong2* sc2 = reinterpret_cast<const ulonglong2*>(scoef);
    unsigned long long cb0 = 0, cb1 = 0;
    unsigned long long accA = 0ull, accB = 0ull;
    int p = 0;

    // coef(p): paired LDS.128, duplicated values -> one load serves 2 coefs
#define COEF(dst)                                                     \
    do {                                                              \
        if ((p & 1) == 0) { ulonglong2 t = sc2[p >> 1]; cb0 = t.x; cb1 = t.y; } \
        dst = (p & 1) ? cb1 : cb0;                                    \
        p++;                                                          \
    } while (0)

#pragma unroll
    for (int x = 0; x < 16; ++x) {
        unsigned long long P;
        COEF(P);                                   // C0(x)
#pragma unroll
        for (int i = x; i < 16; ++i) {
            unsigned long long Q;
            COEF(Q);                               // C1(x,i)
#pragma unroll
            for (int j = i; j < 16; ++j) {
                unsigned long long c2;
                COEF(c2);                          // C2(x,i,j)
                FMA2(Q, c2, F[j], Q);
            }
            FMA2(P, F[i], Q, P);
        }
        if (x & 1) FMA2(accB, F[x], P, accB);
        else       FMA2(accA, F[x], P, accA);
    }
#undef COEF

    ADD2(accA, accA, accB);

    unsigned rl, rh;
    asm("mov.b64 {%0, %1}, %2;" : "=r"(rl), "=r"(rh) : "l"(accA));
    if (n0 < Natoms) out[n0 * 64 + c] = __uint_as_float(rl);
    if (n1 < Natoms) out[n1 * 64 + c] = __uint_as_float(rh);
}

// ---------------------------------------------------------------------------
// Launch. Inputs (metadata order): node_feats, U2, U1, U0, w2, w1, w0.
// ---------------------------------------------------------------------------
extern "C" void kernel_launch(void* const* d_in, const int* in_sizes, int n_in,
                              void* d_out, int out_size) {
    const float* nf = (const float*)d_in[0];
    const float* U2 = (const float*)d_in[1];
    const float* U1 = (const float*)d_in[2];
    const float* U0 = (const float*)d_in[3];
    const float* w2 = (const float*)d_in[4];
    const float* w1 = (const float*)d_in[5];
    const float* w0 = (const float*)d_in[6];
    float* out = (float*)d_out;

    int Natoms = in_sizes[0] / (64 * 16);

    prep_u_kernel<<<NPOS, 128>>>(U2, U1, U0);
    prep_coef_kernel<<<(NPOS * CCH + 255) / 256, 256>>>(w2, w1, w0);

    dim3 grid((Natoms + 511) / 512, CCH);
    sym_contract_kernel<<<grid, 256>>>(nf, out, Natoms);
}